// round 13
// baseline (speedup 1.0000x reference)
#include <cuda_runtime.h>
#include <cuda_fp16.h>
#include <cstdint>
#include <math.h>

#define BATCH 16
#define SEQ   1024
#define EDIM  512
#define NROWS (BATCH*SEQ)
#define TOTALF ((float)((double)BATCH*SEQ*SEQ))
#define TEMP  13.544f
#define EPSV  1e-5f
#define DSCALE 16.0f
#define INV_DSCALE (1.0f/16.0f)

// ---------------- device scratch (no allocations allowed) ------------------
__device__ __half g_h[(size_t)NROWS * EDIM];                 // 16 MB fp16 x
__device__ unsigned short g_d[(size_t)BATCH * SEQ * SEQ];    // 32 MB u16 d*16
__device__ float  g_sq[NROWS];
__device__ double g_sum;
__device__ double g_sumsq;

// ---------------- PTX helpers ----------------------------------------------
__device__ __forceinline__ uint32_t smem_u32(const void* p) {
    uint32_t a;
    asm("{ .reg .u64 t; cvta.to.shared.u64 t, %1; cvt.u32.u64 %0, t; }" : "=r"(a) : "l"(p));
    return a;
}
__device__ __forceinline__ void cp16(uint32_t dst, const void* src) {
    asm volatile("cp.async.cg.shared.global [%0], [%1], 16;" :: "r"(dst), "l"(src));
}
#define CP_COMMIT() asm volatile("cp.async.commit_group;" ::: "memory")
#define CP_WAIT(n)  asm volatile("cp.async.wait_group %0;" :: "n"(n) : "memory")

__device__ __forceinline__ void ldm4(uint32_t* r, uint32_t addr) {
    asm volatile("ldmatrix.sync.aligned.m8n8.x4.shared.b16 {%0,%1,%2,%3}, [%4];"
                 : "=r"(r[0]), "=r"(r[1]), "=r"(r[2]), "=r"(r[3]) : "r"(addr));
}
__device__ __forceinline__ void mma16816(float* c, const uint32_t* a,
                                         uint32_t b0, uint32_t b1) {
    asm volatile("mma.sync.aligned.m16n8k16.row.col.f32.f16.f16.f32 "
                 "{%0,%1,%2,%3}, {%4,%5,%6,%7}, {%8,%9}, {%0,%1,%2,%3};"
                 : "+f"(c[0]), "+f"(c[1]), "+f"(c[2]), "+f"(c[3])
                 : "r"(a[0]), "r"(a[1]), "r"(a[2]), "r"(a[3]), "r"(b0), "r"(b1));
}
__device__ __forceinline__ unsigned short q16(float d) {
    unsigned u = __float2uint_rn(d * DSCALE);
    return (unsigned short)(u > 65535u ? 65535u : u);
}

// ---------------- gram geometry: KC=64, 8 chunks ---------------------------
#define KC        64
#define NCHUNK    (EDIM / KC)              // 8
#define TROWB     144                      // 128B data + 16B pad
#define TILE_B    (128 * TROWB)            // 18432
#define NTILES    2                        // A, B
#define BUF_B     (NTILES * TILE_B)        // 36864
#define SM_SQA    0
#define SM_SQB    512
#define SM_RED    1024
#define SM_REDQ   1056
#define SM_TILES  2048
#define TRPAD     129                      // fp32 staging 128*129*4=66048
#define GRAM_SMEM (SM_TILES + 2 * BUF_B)   // 75776 -> 2 CTAs/SM

// ---------------------------------------------------------------------------
// Kernel 1: fp32 -> fp16 + row squared norms. One warp per TWO rows; all 8
// float4 loads issued upfront for MLP=8 per thread (was latency-bound).
// ---------------------------------------------------------------------------
__global__ __launch_bounds__(256)
void conv_kernel(const float* __restrict__ x) {
    if (blockIdx.x == 0 && threadIdx.x == 0) { g_sum = 0.0; g_sumsq = 0.0; }
    int gw   = (blockIdx.x * blockDim.x + threadIdx.x) >> 5;   // warp id
    int lane = threadIdx.x & 31;
    int r0 = gw * 2;
    if (r0 >= NROWS) return;
    const float4* rA = (const float4*)(x + (size_t)r0 * EDIM);
    const float4* rB = rA + EDIM / 4;
    uint4* oA = (uint4*)(g_h + (size_t)r0 * EDIM);
    uint4* oB = oA + EDIM / 8;

    // uint4 output indices u0 = lane, u1 = lane+32; inputs 2u, 2u+1
    float4 f[8];
    f[0] = rA[2 * lane];      f[1] = rA[2 * lane + 1];
    f[2] = rA[2 * lane + 64]; f[3] = rA[2 * lane + 65];
    f[4] = rB[2 * lane];      f[5] = rB[2 * lane + 1];
    f[6] = rB[2 * lane + 64]; f[7] = rB[2 * lane + 65];

    float s0 = 0.f, s1 = 0.f;
    #pragma unroll
    for (int i = 0; i < 4; i++)
        s0 += f[i].x*f[i].x + f[i].y*f[i].y + f[i].z*f[i].z + f[i].w*f[i].w;
    #pragma unroll
    for (int i = 4; i < 8; i++)
        s1 += f[i].x*f[i].x + f[i].y*f[i].y + f[i].z*f[i].z + f[i].w*f[i].w;

    __half2 h[4];
    h[0] = __floats2half2_rn(f[0].x, f[0].y); h[1] = __floats2half2_rn(f[0].z, f[0].w);
    h[2] = __floats2half2_rn(f[1].x, f[1].y); h[3] = __floats2half2_rn(f[1].z, f[1].w);
    oA[lane] = *(uint4*)h;
    h[0] = __floats2half2_rn(f[2].x, f[2].y); h[1] = __floats2half2_rn(f[2].z, f[2].w);
    h[2] = __floats2half2_rn(f[3].x, f[3].y); h[3] = __floats2half2_rn(f[3].z, f[3].w);
    oA[lane + 32] = *(uint4*)h;
    h[0] = __floats2half2_rn(f[4].x, f[4].y); h[1] = __floats2half2_rn(f[4].z, f[4].w);
    h[2] = __floats2half2_rn(f[5].x, f[5].y); h[3] = __floats2half2_rn(f[5].z, f[5].w);
    oB[lane] = *(uint4*)h;
    h[0] = __floats2half2_rn(f[6].x, f[6].y); h[1] = __floats2half2_rn(f[6].z, f[6].w);
    h[2] = __floats2half2_rn(f[7].x, f[7].y); h[3] = __floats2half2_rn(f[7].z, f[7].w);
    oB[lane + 32] = *(uint4*)h;

    #pragma unroll
    for (int o = 16; o > 0; o >>= 1) {
        s0 += __shfl_xor_sync(0xffffffffu, s0, o);
        s1 += __shfl_xor_sync(0xffffffffu, s1, o);
    }
    if (lane == 0) { g_sq[r0] = s0; g_sq[r0 + 1] = s1; }
}

// ---------------------------------------------------------------------------
// Kernel 2: symmetric fp16 Gram -> u16 d*16. Round-6 loop shape, KC=64,
// register double-buffered fragments (LDSM latency hidden under MMA).
// ---------------------------------------------------------------------------
__device__ __forceinline__ void prefetch_chunk(
    const __half* A, const __half* B, uint32_t sb, int buf, int kc, int tid)
{
    const __half* panels[NTILES] = { A, B };
    int p = tid >> 6, s = tid & 63;
    const char* src = (const char*)panels[p] + kc * (KC * 2);
    uint32_t tb = sb + SM_TILES + buf * BUF_B + p * TILE_B;
    #pragma unroll
    for (int i = 0; i < 16; i++) {
        int idx = i * 64 + s;
        int row = idx >> 3;
        int q   = idx & 7;
        cp16(tb + row * TROWB + q * 16,
             src + (size_t)row * (EDIM * 2) + q * 16);
    }
}

__device__ __forceinline__ void load_frags(uint32_t* aF, uint32_t* bb,
                                           uint32_t base, uint32_t aOff,
                                           uint32_t bOff, uint32_t kb) {
    #pragma unroll
    for (int mi = 0; mi < 4; mi++)
        ldm4(aF + mi * 4, base + 0 * TILE_B + aOff + mi * 16 * TROWB + kb);
    #pragma unroll
    for (int nj = 0; nj < 4; nj++)
        ldm4(bb + nj * 4, base + 1 * TILE_B + bOff + nj * 16 * TROWB + kb);
}

__global__ __launch_bounds__(128, 2)
void gram_tc_kernel() {
    extern __shared__ char smem[];
    const uint32_t sb = smem_u32(smem);
    const int tid  = threadIdx.x;
    const int wid  = tid >> 5;
    const int lane = tid & 31;

    // decode upper-triangle tile pair (8x8 tiles, 36 pairs)
    int p = blockIdx.x, ti = 0;
    while (p >= 8 - ti) { p -= 8 - ti; ti++; }
    const int tj   = ti + p;
    const int b    = blockIdx.z;
    const int row0 = ti * 128;
    const int col0 = tj * 128;
    const int warp_m = (wid >> 1) * 64;
    const int warp_n = (wid & 1) * 64;

    const __half* A = g_h + ((size_t)(b * SEQ + row0)) * EDIM;
    const __half* B = g_h + ((size_t)(b * SEQ + col0)) * EDIM;

    if (tid < 128) {
        ((float*)(smem + SM_SQA))[tid] = g_sq[b * SEQ + row0 + tid];
        ((float*)(smem + SM_SQB))[tid] = g_sq[b * SEQ + col0 + tid];
    }

    float acc[4][8][4];
    #pragma unroll
    for (int mi = 0; mi < 4; mi++)
        #pragma unroll
        for (int ni = 0; ni < 8; ni++)
            #pragma unroll
            for (int k = 0; k < 4; k++) acc[mi][ni][k] = 0.f;

    const uint32_t aOff = (uint32_t)((warp_m + (lane & 15)) * TROWB + (lane >> 4) * 16);
    const uint32_t bOff = (uint32_t)((warp_n + (lane & 7) + ((lane >> 4) << 3)) * TROWB
                                     + ((lane >> 3) & 1) * 16);

    prefetch_chunk(A, B, sb, 0, 0, tid);
    CP_COMMIT();

    #pragma unroll 1
    for (int c = 0; c < NCHUNK; c++) {
        if (c + 1 < NCHUNK) {
            prefetch_chunk(A, B, sb, (c + 1) & 1, c + 1, tid);
            CP_COMMIT();
            CP_WAIT(1);
        } else {
            CP_WAIT(0);
        }
        __syncthreads();

        uint32_t base = sb + SM_TILES + (c & 1) * BUF_B;
        uint32_t aF[2][16], bb[2][16];
        load_frags(aF[0], bb[0], base, aOff, bOff, 0);
        #pragma unroll
        for (int ks = 0; ks < 4; ks++) {
            const int cur = ks & 1;
            if (ks < 3)
                load_frags(aF[cur ^ 1], bb[cur ^ 1], base, aOff, bOff,
                           (uint32_t)(ks + 1) * 32);
            #pragma unroll
            for (int mi = 0; mi < 4; mi++)
                #pragma unroll
                for (int ni = 0; ni < 8; ni++)
                    mma16816(acc[mi][ni], &aF[cur][mi * 4],
                             bb[cur][ni * 2], bb[cur][ni * 2 + 1]);
        }
        __syncthreads();
    }

    // ---------------- epilogue: stage fp32 d in smem, stats, u16 writes ---
    const int g  = lane >> 2;
    const int t4 = lane & 3;
    const float* sqA = (const float*)(smem + SM_SQA);
    const float* sqB = (const float*)(smem + SM_SQB);
    float* trb = (float*)(smem + SM_TILES);
    unsigned short* Dd = g_d + (size_t)b * SEQ * SEQ;
    const bool diag = (ti == tj);
    float fsum = 0.f, fsq = 0.f;
    #pragma unroll
    for (int mi = 0; mi < 4; mi++) {
        #pragma unroll
        for (int h = 0; h < 2; h++) {
            int rl = warp_m + mi * 16 + g + h * 8;
            float sr = sqA[rl];
            #pragma unroll
            for (int ni = 0; ni < 8; ni++) {
                int cl = warp_n + ni * 8 + t4 * 2;
                float d0 = fmaxf(sr + sqB[cl]     - 2.f * acc[mi][ni][2 * h],     0.f);
                float d1 = fmaxf(sr + sqB[cl + 1] - 2.f * acc[mi][ni][2 * h + 1], 0.f);
                if (diag) {                    // exact-zero self distance
                    if (rl == cl)     d0 = 0.f;
                    if (rl == cl + 1) d1 = 0.f;
                }
                fsum += d0 + d1;
                fsq  += d0 * d0 + d1 * d1;
                trb[rl * TRPAD + cl]     = d0;
                trb[rl * TRPAD + cl + 1] = d1;
            }
        }
    }
    __syncthreads();   // trb fully written

    // direct tile (ti,tj): warp-coalesced 256B u16 row stores
    #pragma unroll 4
    for (int r32 = 0; r32 < 32; r32++) {
        int r = wid * 32 + r32;
        const float* tp = trb + r * TRPAD + lane * 4;
        ushort4 u;
        u.x = q16(tp[0]); u.y = q16(tp[1]);
        u.z = q16(tp[2]); u.w = q16(tp[3]);
        *(ushort4*)(Dd + (size_t)(row0 + r) * SEQ + col0 + lane * 4) = u;
    }

    if (!diag) {       // transposed tile (tj,ti): coalesced row writes,
                       // smem column gather (TRPAD=129 -> conflict-free)
        #pragma unroll 4
        for (int r32 = 0; r32 < 32; r32++) {
            int cc = wid * 32 + r32;
            ushort4 u;
            u.x = q16(trb[(lane * 4 + 0) * TRPAD + cc]);
            u.y = q16(trb[(lane * 4 + 1) * TRPAD + cc]);
            u.z = q16(trb[(lane * 4 + 2) * TRPAD + cc]);
            u.w = q16(trb[(lane * 4 + 3) * TRPAD + cc]);
            *(ushort4*)(Dd + (size_t)(col0 + cc) * SEQ + row0 + lane * 4) = u;
        }
        fsum *= 2.f; fsq *= 2.f;
    }

    // stats reduction (fp32 warp -> double CTA -> 2 atomics)
    #pragma unroll
    for (int o = 16; o > 0; o >>= 1) {
        fsum += __shfl_xor_sync(0xffffffffu, fsum, o);
        fsq  += __shfl_xor_sync(0xffffffffu, fsq,  o);
    }
    if (lane == 0) {
        ((double*)(smem + SM_RED))[wid]  = (double)fsum;
        ((double*)(smem + SM_REDQ))[wid] = (double)fsq;
    }
    __syncthreads();
    if (tid == 0) {
        double s = 0.0, q = 0.0;
        #pragma unroll
        for (int k = 0; k < 4; k++) {
            s += ((double*)(smem + SM_RED))[k];
            q += ((double*)(smem + SM_REDQ))[k];
        }
        atomicAdd(&g_sum, s);
        atomicAdd(&g_sumsq, q);
    }
}

// ---------------------------------------------------------------------------
// Kernel 3: warp-per-row softmax. u16 in, fp32 out. Float coef; max-skip.
// ---------------------------------------------------------------------------
__global__ __launch_bounds__(256)
void softmax_kernel(float* __restrict__ dout, const float* __restrict__ gamma) {
    const int wid  = threadIdx.x >> 5;
    const int lane = threadIdx.x & 31;
    const size_t row = (size_t)blockIdx.x * 8 + wid;
    const ushort4* ip = (const ushort4*)(g_d + row * SEQ);
    float4* op = (float4*)(dout + row * SEQ);

    const float fsum0 = (float)g_sum;
    const float fssq  = (float)g_sumsq;
    const float mean  = fsum0 * (1.f / TOTALF);
    const float var   = fssq * (1.f / TOTALF) - mean * mean;
    const float coef  = -gamma[0] * rsqrtf(var + EPSV) * (1.f / TEMP);
    const float c2    = coef * INV_DSCALE;

    float t[32];
    #pragma unroll
    for (int i = 0; i < 8; i++) {
        ushort4 u = ip[lane + 32 * i];
        t[4*i+0] = c2 * (float)u.x;
        t[4*i+1] = c2 * (float)u.y;
        t[4*i+2] = c2 * (float)u.z;
        t[4*i+3] = c2 * (float)u.w;
    }

    float m = 0.f;
    if (coef > 0.f) {            // not taken for gamma>0; correctness guard
        m = -1e30f;
        #pragma unroll
        for (int j = 0; j < 32; j++) m = fmaxf(m, t[j]);
        #pragma unroll
        for (int o = 16; o > 0; o >>= 1) m = fmaxf(m, __shfl_xor_sync(0xffffffffu, m, o));
    }

    float s = 0.f;
    #pragma unroll
    for (int j = 0; j < 32; j++) { t[j] = __expf(t[j] - m); s += t[j]; }
    #pragma unroll
    for (int o = 16; o > 0; o >>= 1) s += __shfl_xor_sync(0xffffffffu, s, o);
    const float inv = 1.f / s;

    #pragma unroll
    for (int i = 0; i < 8; i++) {
        float4 v;
        v.x = t[4*i+0] * inv; v.y = t[4*i+1] * inv;
        v.z = t[4*i+2] * inv; v.w = t[4*i+3] * inv;
        op[lane + 32 * i] = v;
    }
}

// ---------------------------------------------------------------------------
extern "C" void kernel_launch(void* const* d_in, const int* in_sizes, int n_in,
                              void* d_out, int out_size) {
    const float* x     = (const float*)d_in[0];
    const float* gamma = (const float*)d_in[1];
    float* out = (float*)d_out;

    cudaFuncSetAttribute(gram_tc_kernel,
                         cudaFuncAttributeMaxDynamicSharedMemorySize, GRAM_SMEM);

    conv_kernel<<<NROWS * 16 / 256, 256>>>(x);     // 2 rows per warp
    dim3 grid(36, 1, BATCH);
    gram_tc_kernel<<<grid, 128, GRAM_SMEM>>>();
    softmax_kernel<<<NROWS / 8, 256>>>(out, gamma);
}

// round 14
// speedup vs baseline: 1.0630x; 1.0630x over previous
#include <cuda_runtime.h>
#include <cuda_fp16.h>
#include <cstdint>
#include <math.h>

#define BATCH 16
#define SEQ   1024
#define EDIM  512
#define NROWS (BATCH*SEQ)
#define TOTALF ((float)((double)BATCH*SEQ*SEQ))
#define TEMP  13.544f
#define EPSV  1e-5f
#define DSCALE 16.0f
#define INV_DSCALE (1.0f/16.0f)

// ---------------- device scratch (no allocation allowed) -------------------
__device__ __half g_h[(size_t)NROWS * EDIM];                 // 16 MB fp16 x
__device__ unsigned short g_d[(size_t)BATCH * SEQ * SEQ];    // 32 MB u16 d*16
__device__ float  g_sq[NROWS];
__device__ double g_sum;
__device__ double g_sumsq;

// ---------------- PTX helpers ----------------------------------------------
__device__ __forceinline__ uint32_t smem_u32(const void* p) {
    uint32_t a;
    asm("{ .reg .u64 t; cvta.to.shared.u64 t, %1; cvt.u32.u64 %0, t; }" : "=r"(a) : "l"(p));
    return a;
}
__device__ __forceinline__ void cp16(uint32_t dst, const void* src) {
    asm volatile("cp.async.cg.shared.global [%0], [%1], 16;" :: "r"(dst), "l"(src));
}
#define CP_COMMIT() asm volatile("cp.async.commit_group;" ::: "memory")
#define CP_WAIT(n)  asm volatile("cp.async.wait_group %0;" :: "n"(n) : "memory")

__device__ __forceinline__ void ldm4(uint32_t* r, uint32_t addr) {
    asm volatile("ldmatrix.sync.aligned.m8n8.x4.shared.b16 {%0,%1,%2,%3}, [%4];"
                 : "=r"(r[0]), "=r"(r[1]), "=r"(r[2]), "=r"(r[3]) : "r"(addr));
}
__device__ __forceinline__ void mma16816(float* c, const uint32_t* a,
                                         uint32_t b0, uint32_t b1) {
    asm volatile("mma.sync.aligned.m16n8k16.row.col.f32.f16.f16.f32 "
                 "{%0,%1,%2,%3}, {%4,%5,%6,%7}, {%8,%9}, {%0,%1,%2,%3};"
                 : "+f"(c[0]), "+f"(c[1]), "+f"(c[2]), "+f"(c[3])
                 : "r"(a[0]), "r"(a[1]), "r"(a[2]), "r"(a[3]), "r"(b0), "r"(b1));
}
__device__ __forceinline__ unsigned short q16(float d) {
    unsigned u = __float2uint_rn(d * DSCALE);
    return (unsigned short)(u > 65535u ? 65535u : u);
}

// ---------------- gram geometry: KC=64, 8 chunks (round-12 winner) ---------
#define KC        64
#define NCHUNK    (EDIM / KC)              // 8
#define TROWB     144                      // 128B data + 16B pad
#define TILE_B    (128 * TROWB)            // 18432
#define NTILES    2                        // A, B
#define BUF_B     (NTILES * TILE_B)        // 36864
#define SM_SQA    0
#define SM_SQB    512
#define SM_RED    1024
#define SM_REDQ   1056
#define SM_TILES  2048
#define TRPAD     129                      // fp32 staging 128*129*4=66048
#define GRAM_SMEM (SM_TILES + 2 * BUF_B)   // 75776 -> 2 CTAs/SM

// ---------------------------------------------------------------------------
// Kernel 1: fp32 -> fp16 + row squared norms. One warp per TWO rows, all 8
// float4 loads upfront; __ldcs (x is read exactly once -> keep L2 for g_h).
// ---------------------------------------------------------------------------
__global__ __launch_bounds__(256)
void conv_kernel(const float* __restrict__ x) {
    if (blockIdx.x == 0 && threadIdx.x == 0) { g_sum = 0.0; g_sumsq = 0.0; }
    int gw   = (blockIdx.x * blockDim.x + threadIdx.x) >> 5;
    int lane = threadIdx.x & 31;
    int r0 = gw * 2;
    if (r0 >= NROWS) return;
    const float4* rA = (const float4*)(x + (size_t)r0 * EDIM);
    const float4* rB = rA + EDIM / 4;
    uint4* oA = (uint4*)(g_h + (size_t)r0 * EDIM);
    uint4* oB = oA + EDIM / 8;

    float4 f[8];
    f[0] = __ldcs(&rA[2 * lane]);      f[1] = __ldcs(&rA[2 * lane + 1]);
    f[2] = __ldcs(&rA[2 * lane + 64]); f[3] = __ldcs(&rA[2 * lane + 65]);
    f[4] = __ldcs(&rB[2 * lane]);      f[5] = __ldcs(&rB[2 * lane + 1]);
    f[6] = __ldcs(&rB[2 * lane + 64]); f[7] = __ldcs(&rB[2 * lane + 65]);

    float s0 = 0.f, s1 = 0.f;
    #pragma unroll
    for (int i = 0; i < 4; i++)
        s0 += f[i].x*f[i].x + f[i].y*f[i].y + f[i].z*f[i].z + f[i].w*f[i].w;
    #pragma unroll
    for (int i = 4; i < 8; i++)
        s1 += f[i].x*f[i].x + f[i].y*f[i].y + f[i].z*f[i].z + f[i].w*f[i].w;

    __half2 h[4];
    h[0] = __floats2half2_rn(f[0].x, f[0].y); h[1] = __floats2half2_rn(f[0].z, f[0].w);
    h[2] = __floats2half2_rn(f[1].x, f[1].y); h[3] = __floats2half2_rn(f[1].z, f[1].w);
    oA[lane] = *(uint4*)h;
    h[0] = __floats2half2_rn(f[2].x, f[2].y); h[1] = __floats2half2_rn(f[2].z, f[2].w);
    h[2] = __floats2half2_rn(f[3].x, f[3].y); h[3] = __floats2half2_rn(f[3].z, f[3].w);
    oA[lane + 32] = *(uint4*)h;
    h[0] = __floats2half2_rn(f[4].x, f[4].y); h[1] = __floats2half2_rn(f[4].z, f[4].w);
    h[2] = __floats2half2_rn(f[5].x, f[5].y); h[3] = __floats2half2_rn(f[5].z, f[5].w);
    oB[lane] = *(uint4*)h;
    h[0] = __floats2half2_rn(f[6].x, f[6].y); h[1] = __floats2half2_rn(f[6].z, f[6].w);
    h[2] = __floats2half2_rn(f[7].x, f[7].y); h[3] = __floats2half2_rn(f[7].z, f[7].w);
    oB[lane + 32] = *(uint4*)h;

    #pragma unroll
    for (int o = 16; o > 0; o >>= 1) {
        s0 += __shfl_xor_sync(0xffffffffu, s0, o);
        s1 += __shfl_xor_sync(0xffffffffu, s1, o);
    }
    if (lane == 0) { g_sq[r0] = s0; g_sq[r0 + 1] = s1; }
}

// ---------------------------------------------------------------------------
// Kernel 2: symmetric fp16 Gram -> u16 d*16. Round-12 mainloop EXACTLY
// (three restructure attempts regressed; loop is closed). Coalesced u16
// epilogue from round 11.
// ---------------------------------------------------------------------------
__device__ __forceinline__ void prefetch_chunk(
    const __half* A, const __half* B, uint32_t sb, int buf, int kc, int tid)
{
    const __half* panels[NTILES] = { A, B };
    int p = tid >> 6, s = tid & 63;
    const char* src = (const char*)panels[p] + kc * (KC * 2);
    uint32_t tb = sb + SM_TILES + buf * BUF_B + p * TILE_B;
    #pragma unroll
    for (int i = 0; i < 16; i++) {
        int idx = i * 64 + s;
        int row = idx >> 3;
        int q   = idx & 7;
        cp16(tb + row * TROWB + q * 16,
             src + (size_t)row * (EDIM * 2) + q * 16);
    }
}

__global__ __launch_bounds__(128, 2)
void gram_tc_kernel() {
    extern __shared__ char smem[];
    const uint32_t sb = smem_u32(smem);
    const int tid  = threadIdx.x;
    const int wid  = tid >> 5;
    const int lane = tid & 31;

    // decode upper-triangle tile pair (8x8 tiles, 36 pairs)
    int p = blockIdx.x, ti = 0;
    while (p >= 8 - ti) { p -= 8 - ti; ti++; }
    const int tj   = ti + p;
    const int b    = blockIdx.z;
    const int row0 = ti * 128;
    const int col0 = tj * 128;
    const int warp_m = (wid >> 1) * 64;
    const int warp_n = (wid & 1) * 64;

    const __half* A = g_h + ((size_t)(b * SEQ + row0)) * EDIM;
    const __half* B = g_h + ((size_t)(b * SEQ + col0)) * EDIM;

    if (tid < 128) {
        ((float*)(smem + SM_SQA))[tid] = g_sq[b * SEQ + row0 + tid];
        ((float*)(smem + SM_SQB))[tid] = g_sq[b * SEQ + col0 + tid];
    }

    float acc[4][8][4];
    #pragma unroll
    for (int mi = 0; mi < 4; mi++)
        #pragma unroll
        for (int ni = 0; ni < 8; ni++)
            #pragma unroll
            for (int k = 0; k < 4; k++) acc[mi][ni][k] = 0.f;

    const uint32_t aOff = (uint32_t)((warp_m + (lane & 15)) * TROWB + (lane >> 4) * 16);
    const uint32_t bOff = (uint32_t)((warp_n + (lane & 7) + ((lane >> 4) << 3)) * TROWB
                                     + ((lane >> 3) & 1) * 16);

    prefetch_chunk(A, B, sb, 0, 0, tid);
    CP_COMMIT();

    #pragma unroll 1
    for (int c = 0; c < NCHUNK; c++) {
        if (c + 1 < NCHUNK) {
            prefetch_chunk(A, B, sb, (c + 1) & 1, c + 1, tid);
            CP_COMMIT();
            CP_WAIT(1);
        } else {
            CP_WAIT(0);
        }
        __syncthreads();

        uint32_t base = sb + SM_TILES + (c & 1) * BUF_B;
        #pragma unroll
        for (int ks = 0; ks < 4; ks++) {
            const uint32_t kb = ks * 32;
            uint32_t aF[16], bb[16];
            #pragma unroll
            for (int mi = 0; mi < 4; mi++)
                ldm4(&aF[mi * 4], base + 0 * TILE_B + aOff + mi * 16 * TROWB + kb);
            #pragma unroll
            for (int nj = 0; nj < 4; nj++)
                ldm4(&bb[nj * 4], base + 1 * TILE_B + bOff + nj * 16 * TROWB + kb);
            #pragma unroll
            for (int mi = 0; mi < 4; mi++)
                #pragma unroll
                for (int ni = 0; ni < 8; ni++)
                    mma16816(acc[mi][ni], &aF[mi * 4], bb[ni * 2], bb[ni * 2 + 1]);
        }
        __syncthreads();
    }

    // ---------------- epilogue: stage fp32 d in smem, stats, u16 writes ---
    const int g  = lane >> 2;
    const int t4 = lane & 3;
    const float* sqA = (const float*)(smem + SM_SQA);
    const float* sqB = (const float*)(smem + SM_SQB);
    float* trb = (float*)(smem + SM_TILES);
    unsigned short* Dd = g_d + (size_t)b * SEQ * SEQ;
    const bool diag = (ti == tj);
    float fsum = 0.f, fsq = 0.f;
    #pragma unroll
    for (int mi = 0; mi < 4; mi++) {
        #pragma unroll
        for (int h = 0; h < 2; h++) {
            int rl = warp_m + mi * 16 + g + h * 8;
            float sr = sqA[rl];
            #pragma unroll
            for (int ni = 0; ni < 8; ni++) {
                int cl = warp_n + ni * 8 + t4 * 2;
                float d0 = fmaxf(sr + sqB[cl]     - 2.f * acc[mi][ni][2 * h],     0.f);
                float d1 = fmaxf(sr + sqB[cl + 1] - 2.f * acc[mi][ni][2 * h + 1], 0.f);
                if (diag) {                    // exact-zero self distance
                    if (rl == cl)     d0 = 0.f;
                    if (rl == cl + 1) d1 = 0.f;
                }
                fsum += d0 + d1;
                fsq  += d0 * d0 + d1 * d1;
                trb[rl * TRPAD + cl]     = d0;
                trb[rl * TRPAD + cl + 1] = d1;
            }
        }
    }
    __syncthreads();   // trb fully written

    // direct tile (ti,tj): warp-coalesced 256B u16 row stores
    #pragma unroll 4
    for (int r32 = 0; r32 < 32; r32++) {
        int r = wid * 32 + r32;
        const float* tp = trb + r * TRPAD + lane * 4;
        ushort4 u;
        u.x = q16(tp[0]); u.y = q16(tp[1]);
        u.z = q16(tp[2]); u.w = q16(tp[3]);
        *(ushort4*)(Dd + (size_t)(row0 + r) * SEQ + col0 + lane * 4) = u;
    }

    if (!diag) {       // transposed tile (tj,ti): coalesced row writes,
                       // smem column gather (TRPAD=129 -> conflict-free)
        #pragma unroll 4
        for (int r32 = 0; r32 < 32; r32++) {
            int cc = wid * 32 + r32;
            ushort4 u;
            u.x = q16(trb[(lane * 4 + 0) * TRPAD + cc]);
            u.y = q16(trb[(lane * 4 + 1) * TRPAD + cc]);
            u.z = q16(trb[(lane * 4 + 2) * TRPAD + cc]);
            u.w = q16(trb[(lane * 4 + 3) * TRPAD + cc]);
            *(ushort4*)(Dd + (size_t)(col0 + cc) * SEQ + row0 + lane * 4) = u;
        }
        fsum *= 2.f; fsq *= 2.f;
    }

    // stats reduction (fp32 warp -> double CTA -> 2 atomics)
    #pragma unroll
    for (int o = 16; o > 0; o >>= 1) {
        fsum += __shfl_xor_sync(0xffffffffu, fsum, o);
        fsq  += __shfl_xor_sync(0xffffffffu, fsq,  o);
    }
    if (lane == 0) {
        ((double*)(smem + SM_RED))[wid]  = (double)fsum;
        ((double*)(smem + SM_REDQ))[wid] = (double)fsq;
    }
    __syncthreads();
    if (tid == 0) {
        double s = 0.0, q = 0.0;
        #pragma unroll
        for (int k = 0; k < 4; k++) {
            s += ((double*)(smem + SM_RED))[k];
            q += ((double*)(smem + SM_REDQ))[k];
        }
        atomicAdd(&g_sum, s);
        atomicAdd(&g_sumsq, q);
    }
}

// ---------------------------------------------------------------------------
// Kernel 3: warp-per-row softmax. u16 in (L2-resident), fp32 out via __stcs
// streaming stores (never re-read; keep L2 for g_d). Float coef; max-skip.
// ---------------------------------------------------------------------------
__global__ __launch_bounds__(256)
void softmax_kernel(float* __restrict__ dout, const float* __restrict__ gamma) {
    const int wid  = threadIdx.x >> 5;
    const int lane = threadIdx.x & 31;
    const size_t row = (size_t)blockIdx.x * 8 + wid;
    const ushort4* ip = (const ushort4*)(g_d + row * SEQ);
    float4* op = (float4*)(dout + row * SEQ);

    const float fsum0 = (float)g_sum;
    const float fssq  = (float)g_sumsq;
    const float mean  = fsum0 * (1.f / TOTALF);
    const float var   = fssq * (1.f / TOTALF) - mean * mean;
    const float coef  = -gamma[0] * rsqrtf(var + EPSV) * (1.f / TEMP);
    const float c2    = coef * INV_DSCALE;

    float t[32];
    #pragma unroll
    for (int i = 0; i < 8; i++) {
        ushort4 u = ip[lane + 32 * i];
        t[4*i+0] = c2 * (float)u.x;
        t[4*i+1] = c2 * (float)u.y;
        t[4*i+2] = c2 * (float)u.z;
        t[4*i+3] = c2 * (float)u.w;
    }

    float m = 0.f;
    if (coef > 0.f) {            // not taken for gamma>0; correctness guard
        m = -1e30f;
        #pragma unroll
        for (int j = 0; j < 32; j++) m = fmaxf(m, t[j]);
        #pragma unroll
        for (int o = 16; o > 0; o >>= 1) m = fmaxf(m, __shfl_xor_sync(0xffffffffu, m, o));
    }

    float s = 0.f;
    #pragma unroll
    for (int j = 0; j < 32; j++) { t[j] = __expf(t[j] - m); s += t[j]; }
    #pragma unroll
    for (int o = 16; o > 0; o >>= 1) s += __shfl_xor_sync(0xffffffffu, s, o);
    const float inv = 1.f / s;

    #pragma unroll
    for (int i = 0; i < 8; i++) {
        float4 v;
        v.x = t[4*i+0] * inv; v.y = t[4*i+1] * inv;
        v.z = t[4*i+2] * inv; v.w = t[4*i+3] * inv;
        __stcs(&op[lane + 32 * i], v);
    }
}

// ---------------------------------------------------------------------------
extern "C" void kernel_launch(void* const* d_in, const int* in_sizes, int n_in,
                              void* d_out, int out_size) {
    const float* x     = (const float*)d_in[0];
    const float* gamma = (const float*)d_in[1];
    float* out = (float*)d_out;

    cudaFuncSetAttribute(gram_tc_kernel,
                         cudaFuncAttributeMaxDynamicSharedMemorySize, GRAM_SMEM);

    conv_kernel<<<NROWS * 16 / 256, 256>>>(x);     // 2 rows per warp
    dim3 grid(36, 1, BATCH);
    gram_tc_kernel<<<grid, 128, GRAM_SMEM>>>();
    softmax_kernel<<<NROWS / 8, 256>>>(out, gamma);
}

// round 15
// speedup vs baseline: 1.0700x; 1.0065x over previous
#include <cuda_runtime.h>
#include <cuda_fp16.h>
#include <cstdint>
#include <math.h>

#define BATCH 16
#define SEQ   1024
#define EDIM  512
#define NROWS (BATCH*SEQ)
#define TOTALF ((float)((double)BATCH*SEQ*SEQ))
#define TEMP  13.544f
#define EPSV  1e-5f
#define DSCALE 16.0f
#define INV_DSCALE (1.0f/16.0f)

// ---------------- device scratch (no allocation allowed) -------------------
__device__ __half g_h[(size_t)NROWS * EDIM];                 // 16 MB fp16 x
__device__ unsigned short g_d[(size_t)BATCH * SEQ * SEQ];    // 32 MB u16 d*16
__device__ float  g_sq[NROWS];
__device__ double g_sum;
__device__ double g_sumsq;

// ---------------- PTX helpers ----------------------------------------------
__device__ __forceinline__ uint32_t smem_u32(const void* p) {
    uint32_t a;
    asm("{ .reg .u64 t; cvta.to.shared.u64 t, %1; cvt.u32.u64 %0, t; }" : "=r"(a) : "l"(p));
    return a;
}
__device__ __forceinline__ void cp16(uint32_t dst, const void* src) {
    asm volatile("cp.async.cg.shared.global [%0], [%1], 16;" :: "r"(dst), "l"(src));
}
#define CP_COMMIT() asm volatile("cp.async.commit_group;" ::: "memory")
#define CP_WAIT(n)  asm volatile("cp.async.wait_group %0;" :: "n"(n) : "memory")

__device__ __forceinline__ void ldm4(uint32_t* r, uint32_t addr) {
    asm volatile("ldmatrix.sync.aligned.m8n8.x4.shared.b16 {%0,%1,%2,%3}, [%4];"
                 : "=r"(r[0]), "=r"(r[1]), "=r"(r[2]), "=r"(r[3]) : "r"(addr));
}
__device__ __forceinline__ void mma16816(float* c, const uint32_t* a,
                                         uint32_t b0, uint32_t b1) {
    asm volatile("mma.sync.aligned.m16n8k16.row.col.f32.f16.f16.f32 "
                 "{%0,%1,%2,%3}, {%4,%5,%6,%7}, {%8,%9}, {%0,%1,%2,%3};"
                 : "+f"(c[0]), "+f"(c[1]), "+f"(c[2]), "+f"(c[3])
                 : "r"(a[0]), "r"(a[1]), "r"(a[2]), "r"(a[3]), "r"(b0), "r"(b1));
}
__device__ __forceinline__ unsigned short q16(float d) {
    unsigned u = __float2uint_rn(d * DSCALE);
    return (unsigned short)(u > 65535u ? 65535u : u);
}

// ---------------- gram geometry: KC=64, 8 chunks (round-12 winner) ---------
#define KC        64
#define NCHUNK    (EDIM / KC)              // 8
#define TROWB     144                      // 128B data + 16B pad
#define TILE_B    (128 * TROWB)            // 18432
#define NTILES    2                        // A, B
#define BUF_B     (NTILES * TILE_B)        // 36864
#define SM_SQA    0
#define SM_SQB    512
#define SM_RED    1024
#define SM_REDQ   1056
#define SM_TILES  2048
#define TRPAD     129                      // fp32 staging 128*129*4=66048
#define GRAM_SMEM (SM_TILES + 2 * BUF_B)   // 75776 -> 2 CTAs/SM

// ---------------------------------------------------------------------------
// Kernel 1: fp32 -> fp16 + row squared norms. One warp per TWO rows, all 8
// float4 __ldcs loads live simultaneously. __launch_bounds__(256,4) grants
// 64 regs/thread (at 32 regs ptxas serialized the load batch -> MLP << 8).
// ---------------------------------------------------------------------------
__global__ __launch_bounds__(256, 4)
void conv_kernel(const float* __restrict__ x) {
    if (blockIdx.x == 0 && threadIdx.x == 0) { g_sum = 0.0; g_sumsq = 0.0; }
    int gw   = (blockIdx.x * blockDim.x + threadIdx.x) >> 5;
    int lane = threadIdx.x & 31;
    int r0 = gw * 2;
    if (r0 >= NROWS) return;
    const float4* rA = (const float4*)(x + (size_t)r0 * EDIM);
    const float4* rB = rA + EDIM / 4;
    uint4* oA = (uint4*)(g_h + (size_t)r0 * EDIM);
    uint4* oB = oA + EDIM / 8;

    float4 f[8];
    f[0] = __ldcs(&rA[2 * lane]);      f[1] = __ldcs(&rA[2 * lane + 1]);
    f[2] = __ldcs(&rA[2 * lane + 64]); f[3] = __ldcs(&rA[2 * lane + 65]);
    f[4] = __ldcs(&rB[2 * lane]);      f[5] = __ldcs(&rB[2 * lane + 1]);
    f[6] = __ldcs(&rB[2 * lane + 64]); f[7] = __ldcs(&rB[2 * lane + 65]);

    float s0 = 0.f, s1 = 0.f;
    #pragma unroll
    for (int i = 0; i < 4; i++)
        s0 += f[i].x*f[i].x + f[i].y*f[i].y + f[i].z*f[i].z + f[i].w*f[i].w;
    #pragma unroll
    for (int i = 4; i < 8; i++)
        s1 += f[i].x*f[i].x + f[i].y*f[i].y + f[i].z*f[i].z + f[i].w*f[i].w;

    __half2 h[4];
    h[0] = __floats2half2_rn(f[0].x, f[0].y); h[1] = __floats2half2_rn(f[0].z, f[0].w);
    h[2] = __floats2half2_rn(f[1].x, f[1].y); h[3] = __floats2half2_rn(f[1].z, f[1].w);
    oA[lane] = *(uint4*)h;
    h[0] = __floats2half2_rn(f[2].x, f[2].y); h[1] = __floats2half2_rn(f[2].z, f[2].w);
    h[2] = __floats2half2_rn(f[3].x, f[3].y); h[3] = __floats2half2_rn(f[3].z, f[3].w);
    oA[lane + 32] = *(uint4*)h;
    h[0] = __floats2half2_rn(f[4].x, f[4].y); h[1] = __floats2half2_rn(f[4].z, f[4].w);
    h[2] = __floats2half2_rn(f[5].x, f[5].y); h[3] = __floats2half2_rn(f[5].z, f[5].w);
    oB[lane] = *(uint4*)h;
    h[0] = __floats2half2_rn(f[6].x, f[6].y); h[1] = __floats2half2_rn(f[6].z, f[6].w);
    h[2] = __floats2half2_rn(f[7].x, f[7].y); h[3] = __floats2half2_rn(f[7].z, f[7].w);
    oB[lane + 32] = *(uint4*)h;

    #pragma unroll
    for (int o = 16; o > 0; o >>= 1) {
        s0 += __shfl_xor_sync(0xffffffffu, s0, o);
        s1 += __shfl_xor_sync(0xffffffffu, s1, o);
    }
    if (lane == 0) { g_sq[r0] = s0; g_sq[r0 + 1] = s1; }
}

// ---------------------------------------------------------------------------
// Kernel 2: symmetric fp16 Gram -> u16 d*16. Round-12 mainloop EXACTLY
// (three restructure attempts regressed; mainloop is closed). Coalesced u16
// epilogue from round 11.
// ---------------------------------------------------------------------------
__device__ __forceinline__ void prefetch_chunk(
    const __half* A, const __half* B, uint32_t sb, int buf, int kc, int tid)
{
    const __half* panels[NTILES] = { A, B };
    int p = tid >> 6, s = tid & 63;
    const char* src = (const char*)panels[p] + kc * (KC * 2);
    uint32_t tb = sb + SM_TILES + buf * BUF_B + p * TILE_B;
    #pragma unroll
    for (int i = 0; i < 16; i++) {
        int idx = i * 64 + s;
        int row = idx >> 3;
        int q   = idx & 7;
        cp16(tb + row * TROWB + q * 16,
             src + (size_t)row * (EDIM * 2) + q * 16);
    }
}

__global__ __launch_bounds__(128, 2)
void gram_tc_kernel() {
    extern __shared__ char smem[];
    const uint32_t sb = smem_u32(smem);
    const int tid  = threadIdx.x;
    const int wid  = tid >> 5;
    const int lane = tid & 31;

    // decode upper-triangle tile pair (8x8 tiles, 36 pairs)
    int p = blockIdx.x, ti = 0;
    while (p >= 8 - ti) { p -= 8 - ti; ti++; }
    const int tj   = ti + p;
    const int b    = blockIdx.z;
    const int row0 = ti * 128;
    const int col0 = tj * 128;
    const int warp_m = (wid >> 1) * 64;
    const int warp_n = (wid & 1) * 64;

    const __half* A = g_h + ((size_t)(b * SEQ + row0)) * EDIM;
    const __half* B = g_h + ((size_t)(b * SEQ + col0)) * EDIM;

    if (tid < 128) {
        ((float*)(smem + SM_SQA))[tid] = g_sq[b * SEQ + row0 + tid];
        ((float*)(smem + SM_SQB))[tid] = g_sq[b * SEQ + col0 + tid];
    }

    float acc[4][8][4];
    #pragma unroll
    for (int mi = 0; mi < 4; mi++)
        #pragma unroll
        for (int ni = 0; ni < 8; ni++)
            #pragma unroll
            for (int k = 0; k < 4; k++) acc[mi][ni][k] = 0.f;

    const uint32_t aOff = (uint32_t)((warp_m + (lane & 15)) * TROWB + (lane >> 4) * 16);
    const uint32_t bOff = (uint32_t)((warp_n + (lane & 7) + ((lane >> 4) << 3)) * TROWB
                                     + ((lane >> 3) & 1) * 16);

    prefetch_chunk(A, B, sb, 0, 0, tid);
    CP_COMMIT();

    #pragma unroll 1
    for (int c = 0; c < NCHUNK; c++) {
        if (c + 1 < NCHUNK) {
            prefetch_chunk(A, B, sb, (c + 1) & 1, c + 1, tid);
            CP_COMMIT();
            CP_WAIT(1);
        } else {
            CP_WAIT(0);
        }
        __syncthreads();

        uint32_t base = sb + SM_TILES + (c & 1) * BUF_B;
        #pragma unroll
        for (int ks = 0; ks < 4; ks++) {
            const uint32_t kb = ks * 32;
            uint32_t aF[16], bb[16];
            #pragma unroll
            for (int mi = 0; mi < 4; mi++)
                ldm4(&aF[mi * 4], base + 0 * TILE_B + aOff + mi * 16 * TROWB + kb);
            #pragma unroll
            for (int nj = 0; nj < 4; nj++)
                ldm4(&bb[nj * 4], base + 1 * TILE_B + bOff + nj * 16 * TROWB + kb);
            #pragma unroll
            for (int mi = 0; mi < 4; mi++)
                #pragma unroll
                for (int ni = 0; ni < 8; ni++)
                    mma16816(acc[mi][ni], &aF[mi * 4], bb[ni * 2], bb[ni * 2 + 1]);
        }
        __syncthreads();
    }

    // ---------------- epilogue: stage fp32 d in smem, stats, u16 writes ---
    const int g  = lane >> 2;
    const int t4 = lane & 3;
    const float* sqA = (const float*)(smem + SM_SQA);
    const float* sqB = (const float*)(smem + SM_SQB);
    float* trb = (float*)(smem + SM_TILES);
    unsigned short* Dd = g_d + (size_t)b * SEQ * SEQ;
    const bool diag = (ti == tj);
    float fsum = 0.f, fsq = 0.f;
    #pragma unroll
    for (int mi = 0; mi < 4; mi++) {
        #pragma unroll
        for (int h = 0; h < 2; h++) {
            int rl = warp_m + mi * 16 + g + h * 8;
            float sr = sqA[rl];
            #pragma unroll
            for (int ni = 0; ni < 8; ni++) {
                int cl = warp_n + ni * 8 + t4 * 2;
                float d0 = fmaxf(sr + sqB[cl]     - 2.f * acc[mi][ni][2 * h],     0.f);
                float d1 = fmaxf(sr + sqB[cl + 1] - 2.f * acc[mi][ni][2 * h + 1], 0.f);
                if (diag) {                    // exact-zero self distance
                    if (rl == cl)     d0 = 0.f;
                    if (rl == cl + 1) d1 = 0.f;
                }
                fsum += d0 + d1;
                fsq  += d0 * d0 + d1 * d1;
                trb[rl * TRPAD + cl]     = d0;
                trb[rl * TRPAD + cl + 1] = d1;
            }
        }
    }
    __syncthreads();   // trb fully written

    // direct tile (ti,tj): warp-coalesced 256B u16 row stores
    #pragma unroll 4
    for (int r32 = 0; r32 < 32; r32++) {
        int r = wid * 32 + r32;
        const float* tp = trb + r * TRPAD + lane * 4;
        ushort4 u;
        u.x = q16(tp[0]); u.y = q16(tp[1]);
        u.z = q16(tp[2]); u.w = q16(tp[3]);
        *(ushort4*)(Dd + (size_t)(row0 + r) * SEQ + col0 + lane * 4) = u;
    }

    if (!diag) {       // transposed tile (tj,ti): coalesced row writes,
                       // smem column gather (TRPAD=129 -> conflict-free)
        #pragma unroll 4
        for (int r32 = 0; r32 < 32; r32++) {
            int cc = wid * 32 + r32;
            ushort4 u;
            u.x = q16(trb[(lane * 4 + 0) * TRPAD + cc]);
            u.y = q16(trb[(lane * 4 + 1) * TRPAD + cc]);
            u.z = q16(trb[(lane * 4 + 2) * TRPAD + cc]);
            u.w = q16(trb[(lane * 4 + 3) * TRPAD + cc]);
            *(ushort4*)(Dd + (size_t)(col0 + cc) * SEQ + row0 + lane * 4) = u;
        }
        fsum *= 2.f; fsq *= 2.f;
    }

    // stats reduction (fp32 warp -> double CTA -> 2 atomics)
    #pragma unroll
    for (int o = 16; o > 0; o >>= 1) {
        fsum += __shfl_xor_sync(0xffffffffu, fsum, o);
        fsq  += __shfl_xor_sync(0xffffffffu, fsq,  o);
    }
    if (lane == 0) {
        ((double*)(smem + SM_RED))[wid]  = (double)fsum;
        ((double*)(smem + SM_REDQ))[wid] = (double)fsq;
    }
    __syncthreads();
    if (tid == 0) {
        double s = 0.0, q = 0.0;
        #pragma unroll
        for (int k = 0; k < 4; k++) {
            s += ((double*)(smem + SM_RED))[k];
            q += ((double*)(smem + SM_REDQ))[k];
        }
        atomicAdd(&g_sum, s);
        atomicAdd(&g_sumsq, q);
    }
}

// ---------------------------------------------------------------------------
// Kernel 3: warp-per-row softmax. u16 in (L2-resident), fp32 out via __stcs
// streaming stores. Float coef; analytic max-skip (d_ii = 0, coef < 0).
// ---------------------------------------------------------------------------
__global__ __launch_bounds__(256)
void softmax_kernel(float* __restrict__ dout, const float* __restrict__ gamma) {
    const int wid  = threadIdx.x >> 5;
    const int lane = threadIdx.x & 31;
    const size_t row = (size_t)blockIdx.x * 8 + wid;
    const ushort4* ip = (const ushort4*)(g_d + row * SEQ);
    float4* op = (float4*)(dout + row * SEQ);

    const float fsum0 = (float)g_sum;
    const float fssq  = (float)g_sumsq;
    const float mean  = fsum0 * (1.f / TOTALF);
    const float var   = fssq * (1.f / TOTALF) - mean * mean;
    const float coef  = -gamma[0] * rsqrtf(var + EPSV) * (1.f / TEMP);
    const float c2    = coef * INV_DSCALE;

    float t[32];
    #pragma unroll
    for (int i = 0; i < 8; i++) {
        ushort4 u = ip[lane + 32 * i];
        t[4*i+0] = c2 * (float)u.x;
        t[4*i+1] = c2 * (float)u.y;
        t[4*i+2] = c2 * (float)u.z;
        t[4*i+3] = c2 * (float)u.w;
    }

    float m = 0.f;
    if (coef > 0.f) {            // not taken for gamma>0; correctness guard
        m = -1e30f;
        #pragma unroll
        for (int j = 0; j < 32; j++) m = fmaxf(m, t[j]);
        #pragma unroll
        for (int o = 16; o > 0; o >>= 1) m = fmaxf(m, __shfl_xor_sync(0xffffffffu, m, o));
    }

    float s = 0.f;
    #pragma unroll
    for (int j = 0; j < 32; j++) { t[j] = __expf(t[j] - m); s += t[j]; }
    #pragma unroll
    for (int o = 16; o > 0; o >>= 1) s += __shfl_xor_sync(0xffffffffu, s, o);
    const float inv = 1.f / s;

    #pragma unroll
    for (int i = 0; i < 8; i++) {
        float4 v;
        v.x = t[4*i+0] * inv; v.y = t[4*i+1] * inv;
        v.z = t[4*i+2] * inv; v.w = t[4*i+3] * inv;
        __stcs(&op[lane + 32 * i], v);
    }
}

// ---------------------------------------------------------------------------
extern "C" void kernel_launch(void* const* d_in, const int* in_sizes, int n_in,
                              void* d_out, int out_size) {
    const float* x     = (const float*)d_in[0];
    const float* gamma = (const float*)d_in[1];
    float* out = (float*)d_out;

    cudaFuncSetAttribute(gram_tc_kernel,
                         cudaFuncAttributeMaxDynamicSharedMemorySize, GRAM_SMEM);

    conv_kernel<<<NROWS * 16 / 256, 256>>>(x);     // 2 rows per warp
    dim3 grid(36, 1, BATCH);
    gram_tc_kernel<<<grid, 128, GRAM_SMEM>>>();
    softmax_kernel<<<NROWS / 8, 256>>>(out, gamma);
}